// round 9
// baseline (speedup 1.0000x reference)
#include <cuda_runtime.h>
#include <cuda_bf16.h>
#include <cstdint>

#define CH      128
#define NRELS   7
#define KAGG    (NRELS * CH)      // 896 fp32 K held in g_agg
#define KTOT    1408              // 896 rel + 512 virtual root K
#define MAX_TGT 50000
#define NITER   22                // 64 fp32-k per iteration (14 rel + 8 root)
#define STAGES  3

static __device__ float          g_agg[(size_t)MAX_TGT * KAGG];   // ~179 MB
static __device__ int            g_cnt[MAX_TGT * NRELS];
static __device__ __nv_bfloat16  g_Wh[(size_t)CH * KTOT];         // hi bf16, [n][k]
static __device__ __nv_bfloat16  g_Wl[(size_t)CH * KTOT];         // lo bf16, [n][k]

// ===================== helpers ============================================
__device__ __forceinline__ uint32_t smem_u32(const void* p) {
    uint32_t a;
    asm("{ .reg .u64 t; cvta.to.shared.u64 t, %1; cvt.u32.u64 %0, t; }"
        : "=r"(a) : "l"(p));
    return a;
}
__device__ __forceinline__ uint32_t sw128(uint32_t b) { return b ^ ((b >> 3) & 0x70); }

__device__ __forceinline__ void cp16(uint32_t dst, const void* src, bool pred) {
    int sz = pred ? 16 : 0;
    asm volatile("cp.async.cg.shared.global [%0], [%1], 16, %2;"
                 :: "r"(dst), "l"(src), "r"(sz) : "memory");
}
__device__ __forceinline__ void cp_commit() {
    asm volatile("cp.async.commit_group;" ::: "memory");
}

__device__ __forceinline__ float2 lds64(uint32_t a) {
    float2 r;
    asm volatile("ld.shared.v2.f32 {%0,%1}, [%2];" : "=f"(r.x), "=f"(r.y) : "r"(a));
    return r;
}

// scaled fp32 pair -> (hi bf16x2, lo bf16x2); elem0 in low half
__device__ __forceinline__ void cvt_hl(float2 f, float s, uint32_t& h, uint32_t& l) {
    float x = f.x * s, y = f.y * s;
    asm("cvt.rn.bf16x2.f32 %0, %1, %2;" : "=r"(h) : "f"(y), "f"(x));
    float hx = __uint_as_float(h << 16);
    float hy = __uint_as_float(h & 0xffff0000u);
    asm("cvt.rn.bf16x2.f32 %0, %1, %2;" : "=r"(l) : "f"(y - hy), "f"(x - hx));
}

__device__ __forceinline__ void ldsm_x4(uint32_t& r0, uint32_t& r1,
                                        uint32_t& r2, uint32_t& r3, uint32_t addr) {
    asm volatile("ldmatrix.sync.aligned.m8n8.x4.shared.b16 {%0,%1,%2,%3}, [%4];"
                 : "=r"(r0), "=r"(r1), "=r"(r2), "=r"(r3) : "r"(addr));
}
__device__ __forceinline__ void mma16816(float* c, const uint32_t* a, const uint32_t* b) {
    asm volatile("mma.sync.aligned.m16n8k16.row.col.f32.bf16.bf16.f32 "
                 "{%0,%1,%2,%3}, {%4,%5,%6,%7}, {%8,%9}, {%0,%1,%2,%3};"
                 : "+f"(c[0]), "+f"(c[1]), "+f"(c[2]), "+f"(c[3])
                 : "r"(a[0]), "r"(a[1]), "r"(a[2]), "r"(a[3]), "r"(b[0]), "r"(b[1]));
}

// ===================== prep kernels =======================================
__global__ void zero_kernel(int n_tgt) {
    size_t stride = (size_t)gridDim.x * blockDim.x;
    size_t i0 = (size_t)blockIdx.x * blockDim.x + threadIdx.x;
    size_t n4 = (size_t)n_tgt * (KAGG / 4);
    float4 z = make_float4(0.f, 0.f, 0.f, 0.f);
    float4* p = reinterpret_cast<float4*>(g_agg);
    for (size_t i = i0; i < n4; i += stride) p[i] = z;
    size_t nc = (size_t)n_tgt * NRELS;
    for (size_t i = i0; i < nc; i += stride) g_cnt[i] = 0;
}

__global__ void pack_wb_kernel(const float* __restrict__ rel_w,
                               const float* __restrict__ root_w) {
    int idx = blockIdx.x * blockDim.x + threadIdx.x;
    if (idx >= CH * KTOT) return;
    int n = idx / KTOT, k = idx % KTOT;
    int slot = k >> 7, kk = k & 127;
    float w = (slot < NRELS)
                  ? rel_w[((size_t)slot * CH + n) * CH + kk]
                  : root_w[((size_t)(slot - NRELS) * CH + n) * CH + kk];
    __nv_bfloat16 h = __float2bfloat16(w);
    __nv_bfloat16 l = __float2bfloat16(w - __bfloat162float(h));
    g_Wh[(size_t)n * KTOT + k] = h;
    g_Wl[(size_t)n * KTOT + k] = l;
}

__global__ void scatter_kernel(const float4* __restrict__ x_src,
                               const int* __restrict__ e_src,
                               const int* __restrict__ e_dst,
                               const int* __restrict__ e_type,
                               int n_edges) {
    int warp = (blockIdx.x * blockDim.x + threadIdx.x) >> 5;
    int lane = threadIdx.x & 31;
    if (warp >= n_edges) return;
    int s = e_src[warp];
    int d = e_dst[warp];
    int r = e_type[warp];
    float4 v = x_src[(size_t)s * (CH / 4) + lane];
    float* dst = g_agg + (size_t)d * KAGG + r * CH + lane * 4;
    asm volatile("red.global.add.v4.f32 [%0], {%1,%2,%3,%4};"
                 :: "l"(dst), "f"(v.x), "f"(v.y), "f"(v.z), "f"(v.w) : "memory");
    if (lane == 0) atomicAdd(&g_cnt[d * NRELS + r], 1);
}

// ===================== cp.async pipelined split-bf16 GEMM =================
// out = [A_rel | A_root](128 x 1408 fp32) . W^T, 3-product split-bf16:
//   a.w ~= ah.wh + al.wh + ah.wl  (error ~2^-17)
// A staged as raw fp32 (288B-padded rows); convert + scale in registers
// post-LDS. 3-stage cp.async ring, one __syncthreads per iteration.
#define A_STRIDE    288u
#define A_BYTES     (128u * A_STRIDE)         // 36864
#define STAGE_BYTES (A_BYTES + 16384u + 16384u) // 69632
#define SM_STAGE0   6144u                     // after sInv[128][12]
#define SMEM_BYTES  (SM_STAGE0 + STAGES * STAGE_BYTES) // 215040

__global__ __launch_bounds__(256) void gemm_mma_kernel(
    const float* __restrict__ x_tgt,
    const int* __restrict__ t_type,
    const float* __restrict__ root_b,
    float* __restrict__ out, int n_tgt)
{
    extern __shared__ __align__(1024) char smem[];
    float* sInv = reinterpret_cast<float*>(smem);
    uint32_t sbase = smem_u32(smem);

    int tid = threadIdx.x, lane = tid & 31, wid = tid >> 5;
    int wm = wid & 3, wn = wid >> 2;          // 4x2 warp grid (32x64 tiles)
    int m_base = blockIdx.x * 128;

    // --- scale / type-mask table: sInv[row][slot], slots 0..6 rel, 7..10 root
    if (tid < 128) {
        int t = m_base + tid;
        bool v = t < n_tgt;
        int ty = v ? t_type[t] : -1;
#pragma unroll
        for (int r = 0; r < NRELS; r++) {
            int c = v ? g_cnt[t * NRELS + r] : 1;
            sInv[tid * 12 + r] = 1.f / (float)(c > 0 ? c : 1);
        }
#pragma unroll
        for (int s = 0; s < 4; s++)
            sInv[tid * 12 + NRELS + s] = (ty == s) ? 1.f : 0.f;
    }

    // --- staging assignment: one half-row per thread
    int row = tid >> 1, half = tid & 1;
    int t = m_base + row;
    bool valid = t < n_tgt;
    int tcl = valid ? t : 0;
    const float* aggRow = g_agg + (size_t)tcl * KAGG + half * 32;
    const float* xtRow  = x_tgt + (size_t)tcl * CH + half * 32;
    const char*  whRow  = reinterpret_cast<const char*>(g_Wh)
                        + (size_t)row * (KTOT * 2) + half * 64;
    const char*  wlRow  = reinterpret_cast<const char*>(g_Wl)
                        + (size_t)row * (KTOT * 2) + half * 64;
    uint32_t dA = row * A_STRIDE + half * 128u;
    uint32_t dB = sw128((uint32_t)(row * 128 + half * 64));

    auto issue = [&](int idx) {
        uint32_t sb = sbase + SM_STAGE0 + (uint32_t)(idx % STAGES) * STAGE_BYTES;
        const float* as = (idx < 14) ? (aggRow + (size_t)idx * 64)
                                     : (xtRow + ((idx - 14) & 1) * 64);
        uint32_t da = sb + dA;
#pragma unroll
        for (int j = 0; j < 8; j++)
            cp16(da + j * 16, reinterpret_cast<const char*>(as) + j * 16, valid);
        uint32_t dh = sb + A_BYTES + dB;
        uint32_t dl = dh + 16384u;
        const char* hs = whRow + (size_t)idx * 128;
        const char* ls = wlRow + (size_t)idx * 128;
#pragma unroll
        for (int j = 0; j < 4; j++) {
            cp16(dh ^ (j * 16), hs + j * 16, true);
            cp16(dl ^ (j * 16), ls + j * 16, true);
        }
        cp_commit();
    };

    float acc[2][8][4];
#pragma unroll
    for (int i = 0; i < 2; i++)
#pragma unroll
        for (int g = 0; g < 8; g++)
#pragma unroll
            for (int j = 0; j < 4; j++) acc[i][g][j] = 0.f;

    // ldmatrix per-lane coordinates for B (verified layout)
    int b_n  = wn * 64 + (lane >> 4) * 8 + (lane & 7);
    int b_kb = ((lane >> 3) & 1) * 16;
    int a_q  = lane >> 2;                     // fragment row within 8
    int a_c  = (lane & 3) * 2;                // fragment col pair base

    // prologue
    issue(0);
    issue(1);

    for (int it = 0; it < NITER; ++it) {
        if (it == NITER - 1) asm volatile("cp.async.wait_group 0;" ::: "memory");
        else                 asm volatile("cp.async.wait_group 1;" ::: "memory");
        __syncthreads();
        if (it + 2 < NITER) issue(it + 2);

        uint32_t sA = sbase + SM_STAGE0 + (uint32_t)(it % STAGES) * STAGE_BYTES;
        uint32_t sH = sA + A_BYTES;
        uint32_t sL = sH + 16384u;
        int slot = (it < 14) ? (it >> 1) : (NRELS + ((it - 14) >> 1));

        float sc[2][2];
#pragma unroll
        for (int tm = 0; tm < 2; tm++) {
            int r0 = wm * 32 + tm * 16 + a_q;
            sc[tm][0] = sInv[r0 * 12 + slot];
            sc[tm][1] = sInv[(r0 + 8) * 12 + slot];
        }

#pragma unroll
        for (int ks = 0; ks < 4; ks++) {
            uint32_t bh[8][2], bl[8][2];
#pragma unroll
            for (int g2 = 0; g2 < 8; g2 += 2) {
                uint32_t off = sw128((uint32_t)((b_n + g2 * 8) * 128 + ks * 32 + b_kb));
                ldsm_x4(bh[g2][0], bh[g2][1], bh[g2 + 1][0], bh[g2 + 1][1], sH + off);
                ldsm_x4(bl[g2][0], bl[g2][1], bl[g2 + 1][0], bl[g2 + 1][1], sL + off);
            }
#pragma unroll
            for (int tm = 0; tm < 2; tm++) {
                int r0 = wm * 32 + tm * 16 + a_q;
                uint32_t base = sA + r0 * A_STRIDE + (uint32_t)((ks * 16 + a_c) * 4);
                float2 f0 = lds64(base);
                float2 f1 = lds64(base + 8 * A_STRIDE);
                float2 f2 = lds64(base + 32);
                float2 f3 = lds64(base + 8 * A_STRIDE + 32);
                uint32_t ah[4], al[4];
                cvt_hl(f0, sc[tm][0], ah[0], al[0]);
                cvt_hl(f1, sc[tm][1], ah[1], al[1]);
                cvt_hl(f2, sc[tm][0], ah[2], al[2]);
                cvt_hl(f3, sc[tm][1], ah[3], al[3]);
#pragma unroll
                for (int g = 0; g < 8; g++) {
                    mma16816(acc[tm][g], ah, bh[g]);
                    mma16816(acc[tm][g], al, bh[g]);
                    mma16816(acc[tm][g], ah, bl[g]);
                }
            }
        }
    }

    // ---- epilogue: bias + store ----
#pragma unroll
    for (int tm = 0; tm < 2; tm++) {
        int r0 = m_base + wm * 32 + tm * 16 + (lane >> 2);
#pragma unroll
        for (int w = 0; w < 2; w++) {
            int rr = r0 + w * 8;
            if (rr >= n_tgt) continue;
            int tyo = t_type[rr];
            const float* bias = root_b + (size_t)tyo * CH;
            float* orow = out + (size_t)rr * CH;
            int col0 = wn * 64 + (lane & 3) * 2;
#pragma unroll
            for (int g = 0; g < 8; g++) {
                int c = col0 + g * 8;
                float2 o;
                o.x = acc[tm][g][w * 2 + 0] + bias[c];
                o.y = acc[tm][g][w * 2 + 1] + bias[c + 1];
                *reinterpret_cast<float2*>(&orow[c]) = o;
            }
        }
    }
}

// ===================== launch =============================================
extern "C" void kernel_launch(void* const* d_in, const int* in_sizes, int n_in,
                              void* d_out, int out_size) {
    const float* x_src  = (const float*)d_in[0];
    const float* x_tgt  = (const float*)d_in[1];
    const float* rel_w  = (const float*)d_in[2];
    const float* root_w = (const float*)d_in[3];
    const float* root_b = (const float*)d_in[4];
    const int* e_src    = (const int*)d_in[5];
    const int* e_dst    = (const int*)d_in[6];
    const int* e_type   = (const int*)d_in[7];
    const int* t_type   = (const int*)d_in[8];
    float* out = (float*)d_out;

    int n_tgt   = in_sizes[1] / CH;
    int n_edges = in_sizes[5];

    cudaFuncSetAttribute(gemm_mma_kernel,
                         cudaFuncAttributeMaxDynamicSharedMemorySize, SMEM_BYTES);

    zero_kernel<<<2048, 256>>>(n_tgt);
    pack_wb_kernel<<<(CH * KTOT + 255) / 256, 256>>>(rel_w, root_w);
    scatter_kernel<<<(n_edges * 32 + 255) / 256, 256>>>(
        (const float4*)x_src, e_src, e_dst, e_type, n_edges);
    gemm_mma_kernel<<<(n_tgt + 127) / 128, 256, SMEM_BYTES>>>(
        x_tgt, t_type, root_b, out, n_tgt);
}